// round 2
// baseline (speedup 1.0000x reference)
#include <cuda_runtime.h>
#include <cstdint>
#include <cstddef>

#define NP 1024
#define NL 32768
#define NU 64
#define NS 64            /* segments */
#define SEG 512          /* NL/NS */
#define MT 128           /* rows per block in main kernel */
#define KC 64            /* K per chunk */
#define NCH (SEG/KC)     /* 8 */
#define T1 256

__device__ float g_ystart[NP * NS];
__device__ float g_partial[(size_t)NS * NP * NU];

__device__ __forceinline__ float finf()  { return __int_as_float(0x7f800000); }
__device__ __forceinline__ float fninf() { return __int_as_float(0xff800000); }
__device__ __forceinline__ float fclamp(float v, float a, float b) {
    return fminf(fmaxf(v, a), b);
}

__device__ __forceinline__ unsigned long long pack2(float lo, float hi) {
    unsigned long long r;
    asm("mov.b64 %0, {%1, %2};" : "=l"(r) : "f"(lo), "f"(hi));
    return r;
}
__device__ __forceinline__ unsigned long long fma2(unsigned long long a,
                                                   unsigned long long b,
                                                   unsigned long long c) {
    unsigned long long d;
    asm("fma.rn.f32x2 %0, %1, %2, %3;" : "=l"(d) : "l"(a), "l"(b), "l"(c));
    return d;
}

// ---------------------------------------------------------------------------
// Kernel 1: per-row clamp-composition -> y at the 64 segment boundaries.
// y' = clamp(y, a, b); composing clamp(a1,b1) then (a2,b2) gives
// (clamp(a1,a2,b2), clamp(b1,a2,b2)).  j==0 is the clamp (p0,p0).
// Coalesced: stage 4096-float pieces through smem; each thread owns one
// contiguous 16-float unit per piece. Hierarchy: 2048 units -> 256 supers
// (8 units) -> warp lane composes 8 supers (= 2 segments) -> warp scan.
// ---------------------------------------------------------------------------
__global__ __launch_bounds__(T1) void k_boundary(const float* __restrict__ x,
                                                 const float* __restrict__ pw) {
    __shared__ float st[4096];                 // 16KB staging
    __shared__ float uA[2048], uB[2048];       // 16KB unit aggregates
    __shared__ float pA[T1], pB[T1];           // super aggregates

    int p = blockIdx.x;
    int t = threadIdx.x;
    float w = pw[p];
    const float4* src = (const float4*)(x + (size_t)p * NL);
    float4* st4 = (float4*)st;

    float4 r[4];
    #pragma unroll
    for (int i = 0; i < 4; ++i) r[i] = src[t + 256 * i];   // piece 0

    for (int pc = 0; pc < 8; ++pc) {
        if (pc > 0) __syncthreads();           // prior consumers done with st
        #pragma unroll
        for (int i = 0; i < 4; ++i) st4[t + 256 * i] = r[i];
        if (pc < 7) {
            #pragma unroll
            for (int i = 0; i < 4; ++i)
                r[i] = src[(pc + 1) * 1024 + t + 256 * i]; // prefetch next piece
        }
        __syncthreads();

        float A = fninf(), B = finf();
        const float* e = st + t * 16;
        int jbase = pc * 4096 + t * 16;
        #pragma unroll
        for (int k = 0; k < 16; ++k) {
            float v = e[k];
            float a = v * w;
            float b = a + 1.0f;
            if (jbase + k == 0) { a = v; b = v; }
            A = fclamp(A, a, b);
            B = fclamp(B, a, b);
        }
        uA[pc * 256 + t] = A;
        uB[pc * 256 + t] = B;
    }
    __syncthreads();

    // super-units: thread t composes units [8t, 8t+8)  (global unit order)
    {
        float sA = fninf(), sB = finf();
        #pragma unroll
        for (int i = 0; i < 8; ++i) {
            float a = uA[8 * t + i], b = uB[8 * t + i];
            sA = fclamp(sA, a, b);
            sB = fclamp(sB, a, b);
        }
        pA[t] = sA; pB[t] = sB;
    }
    __syncthreads();

    if (t < 32) {
        // lane t owns segments 2t and 2t+1 = supers [8t, 8t+8)
        float cA = fninf(), cB = finf();
        float fA = 0.0f, fB = 0.0f;    // aggregate of first 4 supers (seg 2t)
        #pragma unroll
        for (int i = 0; i < 8; ++i) {
            float a = pA[8 * t + i], b = pB[8 * t + i];
            cA = fclamp(cA, a, b);
            cB = fclamp(cB, a, b);
            if (i == 3) { fA = cA; fB = cB; }
        }
        // inclusive warp scan (non-commutative compose: earlier-then-current)
        #pragma unroll
        for (int d = 1; d < 32; d <<= 1) {
            float oA = __shfl_up_sync(0xffffffffu, cA, d);
            float oB = __shfl_up_sync(0xffffffffu, cB, d);
            if (t >= d) {
                float nA = fclamp(oA, cA, cB);
                float nB = fclamp(oB, cA, cB);
                cA = nA; cB = nB;
            }
        }
        float eA = __shfl_up_sync(0xffffffffu, cA, 1);
        float eB = __shfl_up_sync(0xffffffffu, cB, 1);
        if (t == 0) { eA = fninf(); eB = finf(); }
        float v0 = fclamp(0.0f, eA, eB);       // y entering segment 2t
        float v1 = fclamp(v0, fA, fB);         // y entering segment 2t+1
        g_ystart[p * NS + 2 * t]     = v0;
        g_ystart[p * NS + 2 * t + 1] = v1;
    }
}

// ---------------------------------------------------------------------------
// Kernel 2: fused scan + GEMM.  Block = (128-row tile) x (512-K segment).
// All 128 threads scan (one row each) into ys; GEMM is 8x8 register tiles
// with packed f32x2 FMAs (64 FMA per 4 LDS.128 -> smem/fma balanced).
// ---------------------------------------------------------------------------
__global__ __launch_bounds__(128) void k_main(const float* __restrict__ x,
                                              const float* __restrict__ pw,
                                              const float* __restrict__ kern) {
    __shared__ float ws[KC][NU];   // 16KB kernel tile
    __shared__ float ys[KC][MT];   // 32KB scan outputs

    int tile = blockIdx.x;         // 0..7
    int s    = blockIdx.y;         // 0..63
    int tid  = threadIdx.x;
    int r0   = tile * MT;
    int jseg = s * SEG;

    int ro = 8 * (tid >> 3);       // rows ro..ro+7   (16 groups)
    int co = 8 * (tid & 7);        // cols co..co+7   (8 groups)

    unsigned long long acc[8][4];
    #pragma unroll
    for (int i = 0; i < 8; ++i)
        #pragma unroll
        for (int j = 0; j < 4; ++j) acc[i][j] = 0ull;

    int row = r0 + tid;
    float y = g_ystart[row * NS + s];
    float w = pw[row];
    const float* xp = x + (size_t)row * NL + jseg;

    for (int c = 0; c < NCH; ++c) {
        __syncthreads();           // prior GEMM done reading ws/ys

        // load kernel tile coalesced: 1024 float4, 8 per thread
        const float4* ksrc = (const float4*)(kern + (size_t)(jseg + c * KC) * NU);
        float4* wd = (float4*)ws;
        #pragma unroll
        for (int i = 0; i < 8; ++i) wd[tid + 128 * i] = ksrc[tid + 128 * i];

        // scan this chunk (every thread owns one row)
        {
            const float4* xv = (const float4*)(xp + c * KC);
            int j0 = jseg + c * KC;
            #pragma unroll 4
            for (int q = 0; q < KC / 4; ++q) {
                float4 v = xv[q];
                float vv[4] = {v.x, v.y, v.z, v.w};
                #pragma unroll
                for (int e = 0; e < 4; ++e) {
                    float a = vv[e] * w;
                    float b = a + 1.0f;
                    if (j0 + q * 4 + e == 0) { a = vv[e]; b = vv[e]; }
                    y = fclamp(y, a, b);
                    ys[q * 4 + e][tid] = y;
                }
            }
        }
        __syncthreads();

        // GEMM: 64 FMA per k per thread = 32 fma2, 4 LDS.128
        #pragma unroll 4
        for (int k = 0; k < KC; ++k) {
            float4 y0 = *(const float4*)&ys[k][ro];
            float4 y1 = *(const float4*)&ys[k][ro + 4];
            float4 w0 = *(const float4*)&ws[k][co];
            float4 w1 = *(const float4*)&ws[k][co + 4];
            unsigned long long wp[4] = {
                pack2(w0.x, w0.y), pack2(w0.z, w0.w),
                pack2(w1.x, w1.y), pack2(w1.z, w1.w)
            };
            float yy[8] = {y0.x, y0.y, y0.z, y0.w, y1.x, y1.y, y1.z, y1.w};
            #pragma unroll
            for (int i = 0; i < 8; ++i) {
                unsigned long long yb = pack2(yy[i], yy[i]);
                #pragma unroll
                for (int j = 0; j < 4; ++j)
                    acc[i][j] = fma2(yb, wp[j], acc[i][j]);
            }
        }
    }

    // deterministic per-segment partials, layout [s][p][u]
    #pragma unroll
    for (int i = 0; i < 8; ++i) {
        int pp = r0 + ro + i;
        size_t base = ((size_t)s * NP + pp) * NU + co;
        ulonglong2 v0 = make_ulonglong2(acc[i][0], acc[i][1]);
        ulonglong2 v1 = make_ulonglong2(acc[i][2], acc[i][3]);
        *(ulonglong2*)&g_partial[base]     = v0;
        *(ulonglong2*)&g_partial[base + 4] = v1;
    }
}

// ---------------------------------------------------------------------------
// Kernel 3: fixed-order reduction over segments + bias + tanh.
// ---------------------------------------------------------------------------
__global__ __launch_bounds__(256) void k_reduce(const float* __restrict__ bias,
                                                float* __restrict__ out) {
    int idx = blockIdx.x * blockDim.x + threadIdx.x;   // 0..65535
    int u = idx & (NU - 1);
    float sum = bias[u];
    #pragma unroll 8
    for (int s = 0; s < NS; ++s)
        sum += g_partial[(size_t)s * (NP * NU) + idx];
    out[idx] = tanhf(sum);
}

extern "C" void kernel_launch(void* const* d_in, const int* in_sizes, int n_in,
                              void* d_out, int out_size) {
    const float* x    = (const float*)d_in[0];
    const float* pw   = (const float*)d_in[1];
    const float* kern = (const float*)d_in[2];
    const float* bias = (const float*)d_in[3];
    float* out = (float*)d_out;

    k_boundary<<<NP, T1>>>(x, pw);
    k_main<<<dim3(NP / MT, NS), 128>>>(x, pw, kern);
    k_reduce<<<(NP * NU) / 256, 256>>>(bias, out);
}

// round 4
// speedup vs baseline: 1.7299x; 1.7299x over previous
#include <cuda_runtime.h>
#include <cuda_bf16.h>
#include <cstdint>
#include <cstddef>

#define NP 1024
#define NL 32768
#define NU 64
#define NS 64            /* segments */
#define SEG 512          /* NL/NS */
#define MT 128           /* rows per main block */
#define KC 64            /* K per chunk */
#define NCH (SEG/KC)     /* 8 */

__device__ float g_ystart[NP * NS];
__device__ float g_partial[(size_t)NS * NP * NU];
__device__ __nv_bfloat16 g_bhi[(size_t)NU * NL];   // kernel^T hi, [n][k] K-major
__device__ __nv_bfloat16 g_blo[(size_t)NU * NL];   // kernel^T lo

__device__ __forceinline__ float finf()  { return __int_as_float(0x7f800000); }
__device__ __forceinline__ float fninf() { return __int_as_float(0xff800000); }
__device__ __forceinline__ float fclamp(float v, float a, float b) {
    return fminf(fmaxf(v, a), b);
}
// pack two fp32 -> bf16x2 (e0 low half, e1 high half), round-to-nearest
__device__ __forceinline__ uint32_t bfpack(float e0, float e1) {
    uint32_t r;
    asm("cvt.rn.bf16x2.f32 %0, %1, %2;" : "=r"(r) : "f"(e1), "f"(e0));
    return r;
}
__device__ __forceinline__ uint32_t s2u(const void* p) {
    uint32_t a;
    asm("{ .reg .u64 t; cvta.to.shared.u64 t, %1; cvt.u32.u64 %0, t; }"
        : "=r"(a) : "l"(p));
    return a;
}
__device__ __forceinline__ void ldsm4(uint32_t* r, uint32_t a) {
    asm volatile("ldmatrix.sync.aligned.m8n8.x4.shared.b16 {%0,%1,%2,%3}, [%4];"
        : "=r"(r[0]), "=r"(r[1]), "=r"(r[2]), "=r"(r[3]) : "r"(a));
}
__device__ __forceinline__ void ldsm2(uint32_t& r0, uint32_t& r1, uint32_t a) {
    asm volatile("ldmatrix.sync.aligned.m8n8.x2.shared.b16 {%0,%1}, [%2];"
        : "=r"(r0), "=r"(r1) : "r"(a));
}
__device__ __forceinline__ void mma_bf16(float* d, const uint32_t* a,
                                         uint32_t b0, uint32_t b1) {
    asm volatile(
        "mma.sync.aligned.m16n8k16.row.col.f32.bf16.bf16.f32 "
        "{%0,%1,%2,%3}, {%4,%5,%6,%7}, {%8,%9}, {%0,%1,%2,%3};"
        : "+f"(d[0]), "+f"(d[1]), "+f"(d[2]), "+f"(d[3])
        : "r"(a[0]), "r"(a[1]), "r"(a[2]), "r"(a[3]), "r"(b0), "r"(b1));
}

// ---------------------------------------------------------------------------
// Kernel 0: transpose + bf16-split kernel matrix: [K,N] f32 -> [N,K] bf16 x2
// ---------------------------------------------------------------------------
__global__ __launch_bounds__(256) void k_prep(const float* __restrict__ kern) {
    __shared__ float tile[64][68];
    int k0 = blockIdx.x * 64;
    int t = threadIdx.x;
    int kr = t >> 4;
    int nc = (t & 15) * 4;
    #pragma unroll
    for (int i = 0; i < 4; ++i) {
        float4 v = *(const float4*)&kern[(size_t)(k0 + kr + 16 * i) * NU + nc];
        *(float4*)&tile[kr + 16 * i][nc] = v;
    }
    __syncthreads();
    int n = t & 63;
    int g = t >> 6;               // k sub-group of 16
    uint32_t h[8], l[8];
    #pragma unroll
    for (int i = 0; i < 8; ++i) {
        float a = tile[g * 16 + 2 * i][n];
        float b = tile[g * 16 + 2 * i + 1][n];
        uint32_t hp = bfpack(a, b);
        float ha = __uint_as_float(hp << 16);
        float hb = __uint_as_float(hp & 0xffff0000u);
        h[i] = hp;
        l[i] = bfpack(a - ha, b - hb);
    }
    size_t base = (size_t)n * NL + k0 + g * 16;
    *(uint4*)&g_bhi[base]     = make_uint4(h[0], h[1], h[2], h[3]);
    *(uint4*)&g_bhi[base + 8] = make_uint4(h[4], h[5], h[6], h[7]);
    *(uint4*)&g_blo[base]     = make_uint4(l[0], l[1], l[2], l[3]);
    *(uint4*)&g_blo[base + 8] = make_uint4(l[4], l[5], l[6], l[7]);
}

// ---------------------------------------------------------------------------
// Kernel 1: per-row clamp-composition -> y at the 64 segment boundaries.
// Stride-17 padded staging: LDS reads conflict-free (gcd(17,32)=1).
// ---------------------------------------------------------------------------
__global__ __launch_bounds__(256) void k_boundary(const float* __restrict__ x,
                                                  const float* __restrict__ pw) {
    __shared__ float st[256 * 17];
    __shared__ float uA[2048], uB[2048];
    __shared__ float pA[256], pB[256];

    int p = blockIdx.x;
    int t = threadIdx.x;
    float w = pw[p];
    const float4* src = (const float4*)(x + (size_t)p * NL);

    float4 r[4];
    #pragma unroll
    for (int i = 0; i < 4; ++i) r[i] = src[t + 256 * i];

    for (int pc = 0; pc < 8; ++pc) {
        if (pc > 0) __syncthreads();
        #pragma unroll
        for (int i = 0; i < 4; ++i) {
            int base = 4 * (t + 256 * i);
            int fb = (base >> 4) * 17 + (base & 15);
            st[fb]     = r[i].x;
            st[fb + 1] = r[i].y;
            st[fb + 2] = r[i].z;
            st[fb + 3] = r[i].w;
        }
        if (pc < 7) {
            #pragma unroll
            for (int i = 0; i < 4; ++i)
                r[i] = src[(pc + 1) * 1024 + t + 256 * i];
        }
        __syncthreads();

        float A = fninf(), B = finf();
        const float* e = st + t * 17;
        int jbase = pc * 4096 + t * 16;
        #pragma unroll
        for (int k = 0; k < 16; ++k) {
            float v = e[k];
            float a = v * w;
            float b = a + 1.0f;
            if (jbase + k == 0) { a = v; b = v; }
            A = fclamp(A, a, b);
            B = fclamp(B, a, b);
        }
        uA[pc * 256 + t] = A;
        uB[pc * 256 + t] = B;
    }
    __syncthreads();

    {
        float sA = fninf(), sB = finf();
        #pragma unroll
        for (int i = 0; i < 8; ++i) {
            float a = uA[8 * t + i], b = uB[8 * t + i];
            sA = fclamp(sA, a, b);
            sB = fclamp(sB, a, b);
        }
        pA[t] = sA; pB[t] = sB;
    }
    __syncthreads();

    if (t < 32) {
        float cA = fninf(), cB = finf();
        float fA = 0.0f, fB = 0.0f;
        #pragma unroll
        for (int i = 0; i < 8; ++i) {
            float a = pA[8 * t + i], b = pB[8 * t + i];
            cA = fclamp(cA, a, b);
            cB = fclamp(cB, a, b);
            if (i == 3) { fA = cA; fB = cB; }
        }
        #pragma unroll
        for (int d = 1; d < 32; d <<= 1) {
            float oA = __shfl_up_sync(0xffffffffu, cA, d);
            float oB = __shfl_up_sync(0xffffffffu, cB, d);
            if (t >= d) {
                float nA = fclamp(oA, cA, cB);
                float nB = fclamp(oB, cA, cB);
                cA = nA; cB = nB;
            }
        }
        float eA = __shfl_up_sync(0xffffffffu, cA, 1);
        float eB = __shfl_up_sync(0xffffffffu, cB, 1);
        if (t == 0) { eA = fninf(); eB = finf(); }
        float v0 = fclamp(0.0f, eA, eB);
        float v1 = fclamp(v0, fA, fB);
        g_ystart[p * NS + 2 * t]     = v0;
        g_ystart[p * NS + 2 * t + 1] = v1;
    }
}

// ---------------------------------------------------------------------------
// Kernel 2: fused scan + bf16-split mma.sync GEMM (register accumulators).
// Block = 128 rows x 512-K segment, 128 threads / 4 warps.
// D(fp32) += Ahi*Bhi + Ahi*Blo + Alo*Bhi, per 64-K chunk.
// Smem strides chosen so every 8-lane phase hits distinct banks.
// ---------------------------------------------------------------------------
#define XS_STR 68                          /* floats; 272B row stride */
#define YH_OFF 34816                       /* 128*68*4 */
#define Y_STRB 144                         /* 72 halves */
#define YL_OFF (YH_OFF + 128 * Y_STRB)     /* 53248 */
#define BH_OFF (YL_OFF + 128 * Y_STRB)     /* 71680 */
#define BL_OFF (BH_OFF + 64 * Y_STRB)      /* 80896 */
#define SM_TOT (BL_OFF + 64 * Y_STRB)      /* 90112 */

__global__ __launch_bounds__(128) void k_main(const float* __restrict__ x,
                                              const float* __restrict__ pw) {
    extern __shared__ char smem[];
    float* xs = (float*)smem;
    uint32_t sb = s2u(smem);

    int tile = blockIdx.x;        // 0..7
    int s    = blockIdx.y;        // 0..63
    int t    = threadIdx.x;
    int w    = t >> 5, lane = t & 31;
    int r0   = tile * MT;

    float acc[2][8][4];
    #pragma unroll
    for (int i = 0; i < 2; ++i)
        #pragma unroll
        for (int j = 0; j < 8; ++j)
            #pragma unroll
            for (int q = 0; q < 4; ++q) acc[i][j][q] = 0.0f;

    int row = r0 + t;
    float y  = g_ystart[row * NS + s];
    float pwv = pw[row];

    for (int c = 0; c < NCH; ++c) {
        __syncthreads();          // prior chunk consumers done

        // ---- stage x chunk, coalesced (16 lanes per row) ----
        #pragma unroll
        for (int i = 0; i < 16; ++i) {
            int g = i * 128 + t;
            int r = g >> 4, col = g & 15;
            float4 v = *(const float4*)(x + (size_t)(r0 + r) * NL
                                          + (size_t)s * SEG + c * KC + col * 4);
            *(float4*)(xs + r * XS_STR + col * 4) = v;
        }
        // ---- stage B hi/lo tiles (8 lanes per n-row) ----
        #pragma unroll
        for (int i = 0; i < 4; ++i) {
            int g = i * 128 + t;
            int n = g >> 3, col = g & 7;
            size_t go = (size_t)n * NL + (size_t)s * SEG + c * KC + col * 8;
            *(uint4*)(smem + BH_OFF + n * Y_STRB + col * 16) = *(const uint4*)(g_bhi + go);
            *(uint4*)(smem + BL_OFF + n * Y_STRB + col * 16) = *(const uint4*)(g_blo + go);
        }
        __syncthreads();

        // ---- sequential scan of own row from smem; emit bf16 hi/lo ----
        {
            const float4* xv = (const float4*)(xs + t * XS_STR);
            int j0 = s * SEG + c * KC;
            #pragma unroll
            for (int q = 0; q < 8; ++q) {
                float4 v0 = xv[2 * q], v1 = xv[2 * q + 1];
                float vv[8] = {v0.x, v0.y, v0.z, v0.w, v1.x, v1.y, v1.z, v1.w};
                float ya[8];
                #pragma unroll
                for (int e = 0; e < 8; ++e) {
                    float a = vv[e] * pwv;
                    float b = a + 1.0f;
                    if (j0 + q * 8 + e == 0) { a = vv[e]; b = vv[e]; }
                    y = fclamp(y, a, b);
                    ya[e] = y;
                }
                uint32_t h[4], l[4];
                #pragma unroll
                for (int pp = 0; pp < 4; ++pp) {
                    float e0 = ya[2 * pp], e1 = ya[2 * pp + 1];
                    uint32_t hp = bfpack(e0, e1);
                    float h0 = __uint_as_float(hp << 16);
                    float h1 = __uint_as_float(hp & 0xffff0000u);
                    h[pp] = hp;
                    l[pp] = bfpack(e0 - h0, e1 - h1);
                }
                *(uint4*)(smem + YH_OFF + t * Y_STRB + q * 16) =
                    make_uint4(h[0], h[1], h[2], h[3]);
                *(uint4*)(smem + YL_OFF + t * Y_STRB + q * 16) =
                    make_uint4(l[0], l[1], l[2], l[3]);
            }
        }
        __syncthreads();

        // ---- ldmatrix + mma over 4 k16 steps ----
        #pragma unroll
        for (int kk = 0; kk < 4; ++kk) {
            int k0 = kk * 16;
            uint32_t ah[2][4], al[2][4];
            #pragma unroll
            for (int mt = 0; mt < 2; ++mt) {
                uint32_t ra = sb + YH_OFF
                    + (uint32_t)(w * 32 + mt * 16 + (lane & 7) + ((lane >> 3) & 1) * 8) * Y_STRB
                    + (uint32_t)(k0 + ((lane >> 4) & 1) * 8) * 2;
                ldsm4(ah[mt], ra);
                ldsm4(al[mt], ra + (YL_OFF - YH_OFF));
            }
            #pragma unroll
            for (int nt = 0; nt < 8; ++nt) {
                uint32_t rb = sb + BH_OFF
                    + (uint32_t)(nt * 8 + (lane & 7)) * Y_STRB
                    + (uint32_t)(k0 + ((lane >> 3) & 1) * 8) * 2;
                uint32_t bh0, bh1, bl0, bl1;
                ldsm2(bh0, bh1, rb);
                ldsm2(bl0, bl1, rb + (BL_OFF - BH_OFF));
                #pragma unroll
                for (int mt = 0; mt < 2; ++mt) {
                    mma_bf16(acc[mt][nt], ah[mt], bh0, bh1);
                    mma_bf16(acc[mt][nt], ah[mt], bl0, bl1);
                    mma_bf16(acc[mt][nt], al[mt], bh0, bh1);
                }
            }
        }
    }

    // ---- epilogue: deterministic per-segment partials [s][p][u] ----
    #pragma unroll
    for (int mt = 0; mt < 2; ++mt) {
        int p = r0 + w * 32 + mt * 16 + (lane >> 2);
        #pragma unroll
        for (int nt = 0; nt < 8; ++nt) {
            int u = nt * 8 + (lane & 3) * 2;
            size_t b0 = ((size_t)s * NP + p) * NU + u;
            size_t b1 = ((size_t)s * NP + p + 8) * NU + u;
            *(float2*)&g_partial[b0] = make_float2(acc[mt][nt][0], acc[mt][nt][1]);
            *(float2*)&g_partial[b1] = make_float2(acc[mt][nt][2], acc[mt][nt][3]);
        }
    }
}

// ---------------------------------------------------------------------------
// Kernel 3: fixed-order reduction over segments + bias + tanh.
// ---------------------------------------------------------------------------
__global__ __launch_bounds__(256) void k_reduce(const float* __restrict__ bias,
                                                float* __restrict__ out) {
    int idx = blockIdx.x * blockDim.x + threadIdx.x;
    int u = idx & (NU - 1);
    float sum = bias[u];
    #pragma unroll 8
    for (int s = 0; s < NS; ++s)
        sum += g_partial[(size_t)s * (NP * NU) + idx];
    out[idx] = tanhf(sum);
}

extern "C" void kernel_launch(void* const* d_in, const int* in_sizes, int n_in,
                              void* d_out, int out_size) {
    const float* x    = (const float*)d_in[0];
    const float* pw   = (const float*)d_in[1];
    const float* kern = (const float*)d_in[2];
    const float* bias = (const float*)d_in[3];
    float* out = (float*)d_out;

    cudaFuncSetAttribute(k_main, cudaFuncAttributeMaxDynamicSharedMemorySize, SM_TOT);

    k_prep<<<NL / 64, 256>>>(kern);
    k_boundary<<<NP, 256>>>(x, pw);
    k_main<<<dim3(NP / MT, NS), 128, SM_TOT>>>(x, pw);
    k_reduce<<<(NP * NU) / 256, 256>>>(bias, out);
}

// round 5
// speedup vs baseline: 1.8477x; 1.0681x over previous
#include <cuda_runtime.h>
#include <cuda_bf16.h>
#include <cstdint>
#include <cstddef>

#define NP 1024
#define NL 32768
#define NU 64
#define NS 32            /* segments */
#define SEG 1024         /* NL/NS */
#define NT 8             /* row tiles */
#define MT 128           /* rows per main block */
#define KC 64            /* K per chunk */
#define NCH (SEG/KC)     /* 16 */

__device__ float g_partial[(size_t)NS * NP * NU];
__device__ float2 g_agg[(size_t)NS * NP];          // per-segment row aggregates
__device__ int g_flag[NT * NS];                    // published flags (zero-init)
__device__ __nv_bfloat16 g_bhi[(size_t)NU * NL];   // kernel^T hi, [n][k] K-major
__device__ __nv_bfloat16 g_blo[(size_t)NU * NL];   // kernel^T lo

__device__ __forceinline__ float finf()  { return __int_as_float(0x7f800000); }
__device__ __forceinline__ float fninf() { return __int_as_float(0xff800000); }
__device__ __forceinline__ float fclamp(float v, float a, float b) {
    return fminf(fmaxf(v, a), b);
}
__device__ __forceinline__ uint32_t bfpack(float e0, float e1) {
    uint32_t r;
    asm("cvt.rn.bf16x2.f32 %0, %1, %2;" : "=r"(r) : "f"(e1), "f"(e0));
    return r;
}
__device__ __forceinline__ uint32_t s2u(const void* p) {
    uint32_t a;
    asm("{ .reg .u64 t; cvta.to.shared.u64 t, %1; cvt.u32.u64 %0, t; }"
        : "=r"(a) : "l"(p));
    return a;
}
__device__ __forceinline__ void ldsm4(uint32_t* r, uint32_t a) {
    asm volatile("ldmatrix.sync.aligned.m8n8.x4.shared.b16 {%0,%1,%2,%3}, [%4];"
        : "=r"(r[0]), "=r"(r[1]), "=r"(r[2]), "=r"(r[3]) : "r"(a));
}
__device__ __forceinline__ void ldsm2(uint32_t& r0, uint32_t& r1, uint32_t a) {
    asm volatile("ldmatrix.sync.aligned.m8n8.x2.shared.b16 {%0,%1}, [%2];"
        : "=r"(r0), "=r"(r1) : "r"(a));
}
__device__ __forceinline__ void mma_bf16(float* d, const uint32_t* a,
                                         uint32_t b0, uint32_t b1) {
    asm volatile(
        "mma.sync.aligned.m16n8k16.row.col.f32.bf16.bf16.f32 "
        "{%0,%1,%2,%3}, {%4,%5,%6,%7}, {%8,%9}, {%0,%1,%2,%3};"
        : "+f"(d[0]), "+f"(d[1]), "+f"(d[2]), "+f"(d[3])
        : "r"(a[0]), "r"(a[1]), "r"(a[2]), "r"(a[3]), "r"(b0), "r"(b1));
}

// ---------------------------------------------------------------------------
// Kernel 0: transpose + bf16-split kernel matrix: [K,N] f32 -> [N,K] bf16 x2
// ---------------------------------------------------------------------------
__global__ __launch_bounds__(256) void k_prep(const float* __restrict__ kern) {
    __shared__ float tile[64][68];
    int k0 = blockIdx.x * 64;
    int t = threadIdx.x;
    int kr = t >> 4;
    int nc = (t & 15) * 4;
    #pragma unroll
    for (int i = 0; i < 4; ++i) {
        float4 v = *(const float4*)&kern[(size_t)(k0 + kr + 16 * i) * NU + nc];
        *(float4*)&tile[kr + 16 * i][nc] = v;
    }
    __syncthreads();
    int n = t & 63;
    int g = t >> 6;
    uint32_t h[8], l[8];
    #pragma unroll
    for (int i = 0; i < 8; ++i) {
        float a = tile[g * 16 + 2 * i][n];
        float b = tile[g * 16 + 2 * i + 1][n];
        uint32_t hp = bfpack(a, b);
        float ha = __uint_as_float(hp << 16);
        float hb = __uint_as_float(hp & 0xffff0000u);
        h[i] = hp;
        l[i] = bfpack(a - ha, b - hb);
    }
    size_t base = (size_t)n * NL + k0 + g * 16;
    *(uint4*)&g_bhi[base]     = make_uint4(h[0], h[1], h[2], h[3]);
    *(uint4*)&g_bhi[base + 8] = make_uint4(h[4], h[5], h[6], h[7]);
    *(uint4*)&g_blo[base]     = make_uint4(l[0], l[1], l[2], l[3]);
    *(uint4*)&g_blo[base + 8] = make_uint4(l[4], l[5], l[6], l[7]);
}

// ---------------------------------------------------------------------------
// Kernel 1 (fused): phase 1 per-row clamp aggregates + decoupled lookback
// + phase 2 scan + bf16-split mma GEMM.  Grid 8x32 = 256 blocks, single wave.
// ---------------------------------------------------------------------------
#define XS_STR 68                          /* floats; 272B row stride */
#define YH_OFF 34816                       /* 128*68*4 */
#define Y_STRB 144                         /* 72 halves */
#define YL_OFF (YH_OFF + 128 * Y_STRB)
#define BH_OFF (YL_OFF + 128 * Y_STRB)
#define BL_OFF (BH_OFF + 64 * Y_STRB)
#define SM_TOT (BL_OFF + 64 * Y_STRB)      /* 90112 */

__global__ __launch_bounds__(128) void k_main(const float* __restrict__ x,
                                              const float* __restrict__ pw) {
    extern __shared__ char smem[];
    float* xs = (float*)smem;
    uint32_t sb = s2u(smem);

    int tile = blockIdx.x;        // 0..7
    int s    = blockIdx.y;        // 0..31
    int t    = threadIdx.x;
    int w    = t >> 5, lane = t & 31;
    int r0   = tile * MT;
    int row  = r0 + t;
    float pwv = pw[row];
    const size_t xoff = (size_t)s * SEG;

    // ---------------- phase 1: per-row segment aggregate ----------------
    {
        float A = fninf(), B = finf();
        for (int c = 0; c < NCH; ++c) {
            __syncthreads();
            #pragma unroll
            for (int i = 0; i < 16; ++i) {
                int g = i * 128 + t;
                int r = g >> 4, col = g & 15;
                float4 v = *(const float4*)(x + (size_t)(r0 + r) * NL
                                              + xoff + c * KC + col * 4);
                *(float4*)(xs + r * XS_STR + col * 4) = v;
            }
            __syncthreads();
            const float4* xv = (const float4*)(xs + t * XS_STR);
            int j0 = s * SEG + c * KC;
            #pragma unroll
            for (int q = 0; q < 16; ++q) {
                float4 v = xv[q];
                float vv[4] = {v.x, v.y, v.z, v.w};
                #pragma unroll
                for (int e = 0; e < 4; ++e) {
                    float a = vv[e] * pwv;
                    float b = a + 1.0f;
                    if (j0 + 4 * q + e == 0) { a = vv[e]; b = vv[e]; }
                    A = fclamp(A, a, b);
                    B = fclamp(B, a, b);
                }
            }
        }
        g_agg[(size_t)s * NP + row] = make_float2(A, B);
        __threadfence();
        __syncthreads();
        if (t == 0) atomicExch(&g_flag[tile * NS + s], 1);
    }

    // ---------------- lookback: y entering this segment ----------------
    float y = 0.0f;
    if (s > 0) {
        if (t < s)
            while (atomicAdd(&g_flag[tile * NS + t], 0) == 0) { }
        __syncthreads();
        for (int s2 = 0; s2 < s; ++s2) {
            float2 ab = __ldcg(&g_agg[(size_t)s2 * NP + row]);
            y = fclamp(y, ab.x, ab.y);
        }
    }

    // ---------------- phase 2: scan + GEMM ----------------
    float acc[2][8][4];
    #pragma unroll
    for (int i = 0; i < 2; ++i)
        #pragma unroll
        for (int j = 0; j < 8; ++j)
            #pragma unroll
            for (int q = 0; q < 4; ++q) acc[i][j][q] = 0.0f;

    for (int c = 0; c < NCH; ++c) {
        __syncthreads();
        // stage x chunk (L2-resident re-read), coalesced
        #pragma unroll
        for (int i = 0; i < 16; ++i) {
            int g = i * 128 + t;
            int r = g >> 4, col = g & 15;
            float4 v = *(const float4*)(x + (size_t)(r0 + r) * NL
                                          + xoff + c * KC + col * 4);
            *(float4*)(xs + r * XS_STR + col * 4) = v;
        }
        // stage B hi/lo tiles
        #pragma unroll
        for (int i = 0; i < 4; ++i) {
            int g = i * 128 + t;
            int n = g >> 3, col = g & 7;
            size_t go = (size_t)n * NL + xoff + c * KC + col * 8;
            *(uint4*)(smem + BH_OFF + n * Y_STRB + col * 16) = *(const uint4*)(g_bhi + go);
            *(uint4*)(smem + BL_OFF + n * Y_STRB + col * 16) = *(const uint4*)(g_blo + go);
        }
        __syncthreads();

        // sequential scan of own row from smem; emit bf16 hi/lo
        {
            const float4* xv = (const float4*)(xs + t * XS_STR);
            int j0 = s * SEG + c * KC;
            #pragma unroll
            for (int q = 0; q < 8; ++q) {
                float4 v0 = xv[2 * q], v1 = xv[2 * q + 1];
                float vv[8] = {v0.x, v0.y, v0.z, v0.w, v1.x, v1.y, v1.z, v1.w};
                float ya[8];
                #pragma unroll
                for (int e = 0; e < 8; ++e) {
                    float a = vv[e] * pwv;
                    float b = a + 1.0f;
                    if (j0 + q * 8 + e == 0) { a = vv[e]; b = vv[e]; }
                    y = fclamp(y, a, b);
                    ya[e] = y;
                }
                uint32_t h[4], l[4];
                #pragma unroll
                for (int pp = 0; pp < 4; ++pp) {
                    float e0 = ya[2 * pp], e1 = ya[2 * pp + 1];
                    uint32_t hp = bfpack(e0, e1);
                    float h0 = __uint_as_float(hp << 16);
                    float h1 = __uint_as_float(hp & 0xffff0000u);
                    h[pp] = hp;
                    l[pp] = bfpack(e0 - h0, e1 - h1);
                }
                *(uint4*)(smem + YH_OFF + t * Y_STRB + q * 16) =
                    make_uint4(h[0], h[1], h[2], h[3]);
                *(uint4*)(smem + YL_OFF + t * Y_STRB + q * 16) =
                    make_uint4(l[0], l[1], l[2], l[3]);
            }
        }
        __syncthreads();

        // ldmatrix + mma over 4 k16 steps
        #pragma unroll
        for (int kk = 0; kk < 4; ++kk) {
            int k0 = kk * 16;
            uint32_t ah[2][4], al[2][4];
            #pragma unroll
            for (int mt = 0; mt < 2; ++mt) {
                uint32_t ra = sb + YH_OFF
                    + (uint32_t)(w * 32 + mt * 16 + (lane & 7) + ((lane >> 3) & 1) * 8) * Y_STRB
                    + (uint32_t)(k0 + ((lane >> 4) & 1) * 8) * 2;
                ldsm4(ah[mt], ra);
                ldsm4(al[mt], ra + (YL_OFF - YH_OFF));
            }
            #pragma unroll
            for (int nt = 0; nt < 8; ++nt) {
                uint32_t rb = sb + BH_OFF
                    + (uint32_t)(nt * 8 + (lane & 7)) * Y_STRB
                    + (uint32_t)(k0 + ((lane >> 3) & 1) * 8) * 2;
                uint32_t bh0, bh1, bl0, bl1;
                ldsm2(bh0, bh1, rb);
                ldsm2(bl0, bl1, rb + (BL_OFF - BH_OFF));
                #pragma unroll
                for (int mt = 0; mt < 2; ++mt) {
                    mma_bf16(acc[mt][nt], ah[mt], bh0, bh1);
                    mma_bf16(acc[mt][nt], ah[mt], bl0, bl1);
                    mma_bf16(acc[mt][nt], al[mt], bh0, bh1);
                }
            }
        }
    }

    // epilogue: deterministic per-segment partials [s][p][u]
    #pragma unroll
    for (int mt = 0; mt < 2; ++mt) {
        int p = r0 + w * 32 + mt * 16 + (lane >> 2);
        #pragma unroll
        for (int nt = 0; nt < 8; ++nt) {
            int u = nt * 8 + (lane & 3) * 2;
            size_t b0 = ((size_t)s * NP + p) * NU + u;
            size_t b1 = ((size_t)s * NP + p + 8) * NU + u;
            *(float2*)&g_partial[b0] = make_float2(acc[mt][nt][0], acc[mt][nt][1]);
            *(float2*)&g_partial[b1] = make_float2(acc[mt][nt][2], acc[mt][nt][3]);
        }
    }
}

// ---------------------------------------------------------------------------
// Kernel 2: vectorized fixed-order reduction + bias + tanh; clears flags
// for the next graph replay.
// ---------------------------------------------------------------------------
__global__ __launch_bounds__(256) void k_reduce(const float* __restrict__ bias,
                                                float* __restrict__ out) {
    int gid = blockIdx.x * 256 + threadIdx.x;       // 0..16383 (float4 units)
    if (blockIdx.x == 0 && threadIdx.x < NT * NS)
        g_flag[threadIdx.x] = 0;                    // reset for next replay

    float4 sum = *(const float4*)(bias + ((gid * 4) & (NU - 1)));
    #pragma unroll 8
    for (int s2 = 0; s2 < NS; ++s2) {
        float4 v = *(const float4*)(g_partial + (size_t)s2 * (NP * NU) + (size_t)gid * 4);
        sum.x += v.x; sum.y += v.y; sum.z += v.z; sum.w += v.w;
    }
    float4 r = make_float4(tanhf(sum.x), tanhf(sum.y), tanhf(sum.z), tanhf(sum.w));
    *(float4*)(out + (size_t)gid * 4) = r;
}

extern "C" void kernel_launch(void* const* d_in, const int* in_sizes, int n_in,
                              void* d_out, int out_size) {
    const float* x    = (const float*)d_in[0];
    const float* pw   = (const float*)d_in[1];
    const float* kern = (const float*)d_in[2];
    const float* bias = (const float*)d_in[3];
    float* out = (float*)d_out;

    cudaFuncSetAttribute(k_main, cudaFuncAttributeMaxDynamicSharedMemorySize, SM_TOT);

    k_prep<<<NL / 64, 256>>>(kern);
    k_main<<<dim3(NT, NS), 128, SM_TOT>>>(x, pw);
    k_reduce<<<(NP * NU) / 1024, 256>>>(bias, out);
}